// round 6
// baseline (speedup 1.0000x reference)
#include <cuda_runtime.h>
#include <cuda_bf16.h>
#include <cstdint>

#define B_TOTAL 16384
#define NNODES  200
#define NEDGES  800
#define XF      2600
#define FEATR   2800
#define FEATP   2816          // K padded to 44*64
#define NT1     (FEATP / 64)  // 44

// ---------------- device scratch ----------------
__device__ __align__(16) float g_gbuf[(size_t)B_TOTAL * NNODES];
__device__ __align__(16) float g_a1[(size_t)B_TOTAL * 128];
__device__ float g_norm_dst[NNODES];
__device__ float g_ew[3];
__device__ float g_gcb;
__device__ int   g_csr_off[NNODES + 1];
__device__ int   g_csr_src[NEDGES];
__device__ float g_csr_w[NEDGES];
__device__ __align__(16) __nv_bfloat16 g_w1t_hi[128 * FEATP];
__device__ __align__(16) __nv_bfloat16 g_w1t_lo[128 * FEATP];
__device__ __align__(16) __nv_bfloat16 g_w2t_hi[128 * 128];
__device__ __align__(16) __nv_bfloat16 g_w2t_lo[128 * 128];
__device__ __align__(16) __nv_bfloat16 g_w3t_hi[64 * 128];
__device__ __align__(16) __nv_bfloat16 g_w3t_lo[64 * 128];

// ---------------- helpers ----------------
__device__ __forceinline__ uint32_t smem_to_u32(const void* p) {
    uint32_t a;
    asm("{ .reg .u64 t; cvta.to.shared.u64 t, %1; cvt.u32.u64 %0, t; }" : "=r"(a) : "l"(p));
    return a;
}
#define SWZ(off) ((off) ^ (((off) >> 3) & 0x70))

__device__ __forceinline__ void ldsm4(uint32_t r[4], uint32_t addr) {
    asm volatile("ldmatrix.sync.aligned.m8n8.x4.shared.b16 {%0,%1,%2,%3}, [%4];"
                 : "=r"(r[0]), "=r"(r[1]), "=r"(r[2]), "=r"(r[3]) : "r"(addr));
}
__device__ __forceinline__ void mma16816(float c[4], const uint32_t a[4],
                                         uint32_t b0, uint32_t b1) {
    asm volatile("mma.sync.aligned.m16n8k16.row.col.f32.bf16.bf16.f32 "
                 "{%0,%1,%2,%3}, {%4,%5,%6,%7}, {%8,%9}, {%0,%1,%2,%3};"
                 : "+f"(c[0]), "+f"(c[1]), "+f"(c[2]), "+f"(c[3])
                 : "r"(a[0]), "r"(a[1]), "r"(a[2]), "r"(a[3]), "r"(b0), "r"(b1));
}
__device__ __forceinline__ void cpa16(uint32_t dst, const void* src) {
    asm volatile("cp.async.cg.shared.global [%0], [%1], 16;" :: "r"(dst), "l"(src));
}
#define CPA_COMMIT() asm volatile("cp.async.commit_group;" ::: "memory")
#define CPA_WAIT0()  asm volatile("cp.async.wait_group 0;" ::: "memory")
#define CPA_WAIT1()  asm volatile("cp.async.wait_group 1;" ::: "memory")

__device__ __forceinline__ uint32_t pack_bf16x2(float even, float odd) {
    uint32_t r;
    asm("cvt.rn.bf16x2.f32 %0, %1, %2;" : "=r"(r) : "f"(odd), "f"(even));
    return r;
}
// rounded split (used in mlp2)
__device__ __forceinline__ void split2(float a, float b, uint32_t& hi2, uint32_t& lo2) {
    hi2 = pack_bf16x2(a, b);
    float ah = __uint_as_float(hi2 << 16);
    float bh = __uint_as_float(hi2 & 0xFFFF0000u);
    lo2 = pack_bf16x2(a - ah, b - bh);
}
// truncating split (hi = top 16 bits via PRMT; lo captures residual) — same 3-product accuracy
__device__ __forceinline__ void split2t(float a, float b, uint32_t& hi2, uint32_t& lo2) {
    uint32_t ua = __float_as_uint(a), ub = __float_as_uint(b);
    asm("prmt.b32 %0, %1, %2, 0x7632;" : "=r"(hi2) : "r"(ua), "r"(ub));
    float ar = a - __uint_as_float(ua & 0xFFFF0000u);
    float br = b - __uint_as_float(ub & 0xFFFF0000u);
    lo2 = pack_bf16x2(ar, br);
}
__device__ __forceinline__ float softplusf(float x) {
    return fmaxf(x, 0.f) + log1pf(expf(-fabsf(x)));
}

// ---------------- MMA chunk: warp tile (2*16) x (NTILES*8), K=64 ----------------
template<int NTILES>
__device__ __forceinline__ void mma_chunk(float (&C)[2][NTILES][4],
                                          uint32_t a_hi, uint32_t a_lo,
                                          uint32_t b_hi, uint32_t b_lo,
                                          int wm_base, int wn_base, int lane) {
    const int lr = (lane & 7) + ((lane >> 3) & 1) * 8;
    const int lh = (lane >> 4) * 16;
    #pragma unroll
    for (int kk = 0; kk < 4; kk++) {
        uint32_t ah[2][4], al[2][4];
        #pragma unroll
        for (int mt = 0; mt < 2; mt++) {
            uint32_t off = SWZ((uint32_t)((wm_base + mt * 16 + lr) * 128 + kk * 32 + lh));
            ldsm4(ah[mt], a_hi + off);
            ldsm4(al[mt], a_lo + off);
        }
        #pragma unroll
        for (int ng = 0; ng < NTILES / 2; ng++) {
            uint32_t off = SWZ((uint32_t)((wn_base + ng * 16 + lr) * 128 + kk * 32 + lh));
            uint32_t bh[4], bl[4];
            ldsm4(bh, b_hi + off);
            ldsm4(bl, b_lo + off);
            #pragma unroll
            for (int half = 0; half < 2; half++) {
                const int nt = ng * 2 + half;
                #pragma unroll
                for (int mt = 0; mt < 2; mt++) {
                    mma16816(C[mt][nt], ah[mt], bh[half], bh[half + 2]);
                    mma16816(C[mt][nt], ah[mt], bl[half], bl[half + 2]);
                    mma16816(C[mt][nt], al[mt], bh[half], bh[half + 2]);
                }
            }
        }
    }
}

// ---------------- prep: graph (block 0) + weight transpose/split (all) ----------------
__global__ void prep_kernel(const int* __restrict__ es, const int* __restrict__ ed,
                            const float* __restrict__ emb, const float* __restrict__ gcw,
                            const float* __restrict__ gcb,
                            const float* __restrict__ W1, const float* __restrict__ W2,
                            const float* __restrict__ W3) {
    const int tid = threadIdx.x;
    if (blockIdx.x == 0) {
        __shared__ int cnto[NNODES], cnti[NNODES], pos[NNODES];
        for (int n = tid; n < NNODES; n += 256) { cnto[n] = 0; cnti[n] = 0; }
        __syncthreads();
        for (int e = tid; e < NEDGES; e += 256) {
            atomicAdd(&cnto[es[e]], 1);
            atomicAdd(&cnti[ed[e]], 1);
        }
        __syncthreads();
        for (int n = tid; n < NNODES; n += 256)
            g_norm_dst[n] = rsqrtf((float)max(cnti[n], 1));
        if (tid < 3) {
            float s = 0.f;
            #pragma unroll
            for (int j = 0; j < 5; j++) s += emb[tid * 5 + j] * gcw[j];
            g_ew[tid] = s;
        }
        if (tid == 0) {
            g_gcb = gcb[0];
            int off = 0;
            for (int d = 0; d < NNODES; d++) { g_csr_off[d] = off; pos[d] = off; off += cnti[d]; }
            g_csr_off[NNODES] = off;
        }
        __syncthreads();
        for (int e = tid; e < NEDGES; e += 256) {
            int d = ed[e], s = es[e];
            int p = atomicAdd(&pos[d], 1);
            g_csr_src[p] = s;
            g_csr_w[p] = rsqrtf((float)max(cnto[s], 1));
        }
    }
    const int T1 = 128 * FEATP, T2 = 128 * 128, T3 = 64 * 128;
    for (int i = blockIdx.x * blockDim.x + tid; i < T1 + T2 + T3;
         i += gridDim.x * blockDim.x) {
        float v;
        __nv_bfloat16 *ph, *pl;
        if (i < T1) {
            int k = i % FEATP;
            int n = i / FEATP;
            v = (k < FEATR) ? W1[(size_t)k * 128 + n] : 0.f;
            ph = g_w1t_hi + i; pl = g_w1t_lo + i;
        } else if (i < T1 + T2) {
            int j = i - T1;
            int n = j >> 7, k = j & 127;
            v = W2[k * 128 + n];
            ph = g_w2t_hi + j; pl = g_w2t_lo + j;
        } else {
            int j = i - T1 - T2;
            int n = j >> 7, k = j & 127;
            v = W3[k * 64 + n];
            ph = g_w3t_hi + j; pl = g_w3t_lo + j;
        }
        __nv_bfloat16 h = __float2bfloat16(v);
        *ph = h;
        *pl = __float2bfloat16(v - __bfloat162float(h));
    }
}

#define GC_ROWS 8
__global__ __launch_bounds__(256) void gconv_kernel(const int* __restrict__ apps) {
    __shared__ float hw[GC_ROWS][NNODES];
    const int b0 = blockIdx.x * GC_ROWS;
    const int tid = threadIdx.x;
    for (int i = tid; i < GC_ROWS * NNODES; i += 256) {
        int r = i / NNODES, n = i % NNODES;
        hw[r][n] = g_ew[apps[(size_t)(b0 + r) * NNODES + n]];
    }
    __syncthreads();
    const float gcb = g_gcb;
    for (int i = tid; i < GC_ROWS * NNODES; i += 256) {
        int r = i / NNODES, d = i % NNODES;
        int o0 = g_csr_off[d], o1 = g_csr_off[d + 1];
        float s = 0.f;
        for (int e = o0; e < o1; e++) s += g_csr_w[e] * hw[r][g_csr_src[e]];
        g_gbuf[(size_t)(b0 + r) * NNODES + d] = g_norm_dst[d] * s + gcb;
    }
}

// ================= GEMM1: a1 = softplus(feat @ W1 + b1) =================
// 256 threads, BM=128, BN=128, warp tile 32x64, 3-stage B + 2-stage A pipeline.
#define G1_OFF_B1 0
#define G1_OFF_A  1024                   // 2 stages x (hi 16K + lo 16K) = 64KB
#define G1_OFF_BW (1024 + 65536)         // 3 stages x (hi 16K + lo 16K) = 96KB
#define G1_SMEM   (1024 + 65536 + 98304)

// A chunk load: each thread owns row = tid>>1, 32 k-floats at kq0 = (tid&1)*32
__device__ __forceinline__ void g1_lda(float4 (&pf)[8], const float* __restrict__ xr,
                                       const float* __restrict__ gr, int k0, int kq0) {
    if (k0 + 63 < XF) {
        #pragma unroll
        for (int j = 0; j < 8; j++) pf[j] = *(const float4*)(xr + k0 + kq0 + j * 4);
    } else {
        #pragma unroll
        for (int j = 0; j < 8; j++) {
            const int k = k0 + kq0 + j * 4;
            if (k + 3 < XF)       pf[j] = *(const float4*)(xr + k);
            else if (k < FEATR)   pf[j] = *(const float4*)(gr + (k - XF));
            else                  pf[j] = make_float4(0.f, 0.f, 0.f, 0.f);
        }
    }
}
// convert + store: 32 floats -> 4x uint4 hi + 4x uint4 lo (swizzled)
__device__ __forceinline__ void g1_sta(const float4 (&pf)[8], char* Ah, char* Al,
                                       int row, int kq0) {
    #pragma unroll
    for (int q = 0; q < 4; q++) {
        const float4 f0 = pf[q * 2], f1 = pf[q * 2 + 1];
        uint4 h, l;
        split2t(f0.x, f0.y, h.x, l.x);
        split2t(f0.z, f0.w, h.y, l.y);
        split2t(f1.x, f1.y, h.z, l.z);
        split2t(f1.z, f1.w, h.w, l.w);
        const uint32_t off = SWZ((uint32_t)(row * 128 + (kq0 + q * 8) * 2));
        *(uint4*)(Ah + off) = h;
        *(uint4*)(Al + off) = l;
    }
}

__global__ __launch_bounds__(256, 1)
void gemm1_kernel(const float* __restrict__ x, const float* __restrict__ b1g) {
    extern __shared__ char sm[];
    const uint32_t su = smem_to_u32(sm);
    const int tid = threadIdx.x;
    const int wid = tid >> 5;
    const int lane = tid & 31;
    const int b0 = blockIdx.x * 128;

    float* sb1 = (float*)(sm + G1_OFF_B1);
    if (tid < 128) sb1[tid] = b1g[tid];

    // A stages
    char* pAh[2] = { sm + G1_OFF_A,          sm + G1_OFF_A + 32768 };
    char* pAl[2] = { sm + G1_OFF_A + 16384,  sm + G1_OFF_A + 49152 };
    const uint32_t uAh[2] = { su + G1_OFF_A,         su + G1_OFF_A + 32768 };
    const uint32_t uAl[2] = { su + G1_OFF_A + 16384, su + G1_OFF_A + 49152 };
    // B stages (3)
    uint32_t uBh[3], uBl[3];
    #pragma unroll
    for (int s = 0; s < 3; s++) {
        uBh[s] = su + G1_OFF_BW + s * 32768;
        uBl[s] = su + G1_OFF_BW + s * 32768 + 16384;
    }

    // A loader mapping
    const int arow = tid >> 1;
    const int kq0  = (tid & 1) * 32;
    const float* xr = x + (size_t)(b0 + arow) * XF;
    const float* gr = g_gbuf + (size_t)(b0 + arow) * NNODES;

    // B loader: 4 vec16 per tile per thread (1024 vec / 256 thr)
    uint32_t bofs[4];
    const __nv_bfloat16* gh[4];
    const __nv_bfloat16* gl[4];
    #pragma unroll
    for (int i = 0; i < 4; i++) {
        const int v = tid + i * 256;
        bofs[i] = SWZ((uint32_t)((v >> 3) * 128 + (v & 7) * 16));
        gh[i] = g_w1t_hi + (size_t)(v >> 3) * FEATP + (v & 7) * 8;
        gl[i] = g_w1t_lo + (size_t)(v >> 3) * FEATP + (v & 7) * 8;
    }

    const int wm = (wid >> 1) * 32;   // 4 M-groups of 32
    const int wn = (wid & 1) * 64;    // 2 N-groups of 64

    float C[2][8][4];
    #pragma unroll
    for (int i = 0; i < 2; i++)
        #pragma unroll
        for (int j = 0; j < 8; j++)
            #pragma unroll
            for (int q = 0; q < 4; q++) C[i][j][q] = 0.f;

    float4 pf[8];
    // ---- prologue ----
    // B stages 0 and 1
    #pragma unroll
    for (int i = 0; i < 4; i++) { cpa16(uBh[0] + bofs[i], gh[i]); cpa16(uBl[0] + bofs[i], gl[i]); }
    CPA_COMMIT();
    #pragma unroll
    for (int i = 0; i < 4; i++) { cpa16(uBh[1] + bofs[i], gh[i] + 64); cpa16(uBl[1] + bofs[i], gl[i] + 64); }
    CPA_COMMIT();
    // A chunk 0 -> stage 0 ; A chunk 1 -> regs
    g1_lda(pf, xr, gr, 0, kq0);
    g1_sta(pf, pAh[0], pAl[0], arow, kq0);
    g1_lda(pf, xr, gr, 64, kq0);
    CPA_WAIT1();          // B stage 0 ready
    __syncthreads();

    // ---- mainloop ----
    for (int t = 0; t < NT1; t++) {
        const int cur = t & 1;
        const int bs = t - (t / 3) * 3;          // t % 3
        const bool more2 = (t + 2 < NT1);
        if (more2) {
            const int koff = (t + 2) * 64;
            const int ns = (t + 2) - ((t + 2) / 3) * 3;
            #pragma unroll
            for (int i = 0; i < 4; i++) {
                cpa16(uBh[ns] + bofs[i], gh[i] + koff);
                cpa16(uBl[ns] + bofs[i], gl[i] + koff);
            }
            CPA_COMMIT();
        }
        if (t + 1 < NT1)
            g1_sta(pf, pAh[cur ^ 1], pAl[cur ^ 1], arow, kq0);   // store chunk t+1
        if (more2)
            g1_lda(pf, xr, gr, (t + 2) * 64, kq0);               // load chunk t+2
        mma_chunk<8>(C, uAh[cur], uAl[cur], uBh[bs], uBl[bs], wm, wn, lane);
        if (more2) CPA_WAIT1(); else CPA_WAIT0();                // B stage t+1 ready
        __syncthreads();
    }

    // ---- epilogue: bias + softplus -> g_a1 (f32) ----
    {
        const int r0 = wm + (lane >> 2);
        const int c0 = wn + (lane & 3) * 2;
        #pragma unroll
        for (int mt = 0; mt < 2; mt++) {
            #pragma unroll
            for (int nt = 0; nt < 8; nt++) {
                const int c = c0 + nt * 8;
                const float bb0 = sb1[c], bb1 = sb1[c + 1];
                float2 v01 = make_float2(softplusf(C[mt][nt][0] + bb0),
                                         softplusf(C[mt][nt][1] + bb1));
                float2 v23 = make_float2(softplusf(C[mt][nt][2] + bb0),
                                         softplusf(C[mt][nt][3] + bb1));
                *(float2*)(g_a1 + (size_t)(b0 + r0 + mt * 16) * 128 + c) = v01;
                *(float2*)(g_a1 + (size_t)(b0 + r0 + mt * 16 + 8) * 128 + c) = v23;
            }
        }
    }
}

// ================= kernel 2: layers 2-4 =================
#define M2_OFF_B2 0
#define M2_OFF_B3 512
#define M2_OFF_B4 768
#define M2_OFF_W4 1024
#define M2_OFF_A  2048
#define M2_OFF_BW (2048 + 32768)
#define M2_SMEM   (2048 + 32768 + 65536)

__device__ __forceinline__ void m2_cpa_W(const __nv_bfloat16* __restrict__ W, int ldk,
                                         int k0, uint32_t dst, int nrows, int tid) {
    const int nv = nrows * 8;
    for (int v = tid; v < nv; v += 256) {
        const int n = v >> 3, kq = (v & 7) * 8;
        cpa16(dst + SWZ((uint32_t)(n * 128 + kq * 2)), W + (size_t)n * ldk + k0 + kq);
    }
}

__device__ __forceinline__ void m2_epi_split(float (&C)[2][4][4], const float* bias,
                                             char* dhi, char* dlo,
                                             int wm_base, int wn_base, int lane) {
    const int r0 = wm_base + (lane >> 2);
    const int c0 = wn_base + (lane & 3) * 2;
    #pragma unroll
    for (int mt = 0; mt < 2; mt++) {
        #pragma unroll
        for (int nt = 0; nt < 4; nt++) {
            const int n = c0 + nt * 8;
            const int chunk = n >> 6, col = n & 63;
            const float b0 = bias[n], b1 = bias[n + 1];
            char* th = dhi + chunk * 8192;
            char* tl = dlo + chunk * 8192;
            {
                float v0 = softplusf(C[mt][nt][0] + b0);
                float v1 = softplusf(C[mt][nt][1] + b1);
                uint32_t h, l;
                split2(v0, v1, h, l);
                const uint32_t off = SWZ((uint32_t)((r0 + mt * 16) * 128 + col * 2));
                *(uint32_t*)(th + off) = h;
                *(uint32_t*)(tl + off) = l;
            }
            {
                float v0 = softplusf(C[mt][nt][2] + b0);
                float v1 = softplusf(C[mt][nt][3] + b1);
                uint32_t h, l;
                split2(v0, v1, h, l);
                const uint32_t off = SWZ((uint32_t)((r0 + mt * 16 + 8) * 128 + col * 2));
                *(uint32_t*)(th + off) = h;
                *(uint32_t*)(tl + off) = l;
            }
        }
    }
}

__global__ __launch_bounds__(256, 2)
void mlp2_kernel(const float* __restrict__ b2g, const float* __restrict__ b3g,
                 const float* __restrict__ b4g, const float* __restrict__ W4g,
                 float* __restrict__ out) {
    extern __shared__ char sm[];
    const uint32_t su = smem_to_u32(sm);
    const int tid = threadIdx.x;
    const int wid = tid >> 5;
    const int lane = tid & 31;
    const int b0 = blockIdx.x * 64;

    float* sb2 = (float*)(sm + M2_OFF_B2);
    float* sb3 = (float*)(sm + M2_OFF_B3);
    float* sb4 = (float*)(sm + M2_OFF_B4);
    float* sW4 = (float*)(sm + M2_OFF_W4);
    if (tid < 128) { sb2[tid] = b2g[tid]; sW4[tid] = W4g[tid]; }
    if (tid < 64) sb3[tid] = b3g[tid];
    if (tid < 2) sb4[tid] = b4g[tid];

    char* pAh[2] = { sm + M2_OFF_A,          sm + M2_OFF_A + 8192 };
    char* pAl[2] = { sm + M2_OFF_A + 16384,  sm + M2_OFF_A + 24576 };
    const uint32_t uAh[2] = { su + M2_OFF_A,         su + M2_OFF_A + 8192 };
    const uint32_t uAl[2] = { su + M2_OFF_A + 16384, su + M2_OFF_A + 24576 };
    const uint32_t uBh[2] = { su + M2_OFF_BW,         su + M2_OFF_BW + 16384 };
    const uint32_t uBl[2] = { su + M2_OFF_BW + 32768, su + M2_OFF_BW + 49152 };

    m2_cpa_W(g_w2t_hi, 128, 0,  uBh[0], 128, tid);
    m2_cpa_W(g_w2t_hi, 128, 64, uBh[1], 128, tid);
    m2_cpa_W(g_w2t_lo, 128, 0,  uBl[0], 128, tid);
    m2_cpa_W(g_w2t_lo, 128, 64, uBl[1], 128, tid);
    CPA_COMMIT();

    {
        const int row = tid >> 2;
        const int kq0 = (tid & 3) * 16;
        const float* ar = g_a1 + (size_t)(b0 + row) * 128;
        #pragma unroll
        for (int c = 0; c < 2; c++) {
            #pragma unroll
            for (int j = 0; j < 4; j++) {
                const int kl = kq0 + j * 4;
                float4 f = *(const float4*)(ar + c * 64 + kl);
                uint32_t h01, l01, h23, l23;
                split2(f.x, f.y, h01, l01);
                split2(f.z, f.w, h23, l23);
                const uint32_t off = SWZ((uint32_t)(row * 128 + kl * 2));
                *(uint2*)(pAh[c] + off) = make_uint2(h01, h23);
                *(uint2*)(pAl[c] + off) = make_uint2(l01, l23);
            }
        }
    }
    CPA_WAIT0();
    __syncthreads();

    const int wm = (wid >> 2) * 32;
    const int wn = (wid & 3) * 32;

    float C[2][4][4];
    #pragma unroll
    for (int i = 0; i < 2; i++)
        #pragma unroll
        for (int j = 0; j < 4; j++)
            #pragma unroll
            for (int q = 0; q < 4; q++) C[i][j][q] = 0.f;
    #pragma unroll
    for (int c = 0; c < 2; c++)
        mma_chunk<4>(C, uAh[c], uAl[c], uBh[c], uBl[c], wm, wn, lane);
    __syncthreads();

    m2_epi_split(C, sb2, sm + M2_OFF_A, sm + M2_OFF_A + 16384, wm, wn, lane);
    m2_cpa_W(g_w3t_hi, 128, 0,  su + M2_OFF_BW,         64, tid);
    m2_cpa_W(g_w3t_hi, 128, 64, su + M2_OFF_BW + 8192,  64, tid);
    m2_cpa_W(g_w3t_lo, 128, 0,  su + M2_OFF_BW + 16384, 64, tid);
    m2_cpa_W(g_w3t_lo, 128, 64, su + M2_OFF_BW + 24576, 64, tid);
    CPA_COMMIT();
    CPA_WAIT0();
    __syncthreads();

    const int wn3 = (wid & 3) * 16;
    float C3[2][2][4];
    #pragma unroll
    for (int i = 0; i < 2; i++)
        #pragma unroll
        for (int j = 0; j < 2; j++)
            #pragma unroll
            for (int q = 0; q < 4; q++) C3[i][j][q] = 0.f;
    #pragma unroll
    for (int c = 0; c < 2; c++)
        mma_chunk<2>(C3, uAh[c], uAl[c],
                     su + M2_OFF_BW + c * 8192, su + M2_OFF_BW + 16384 + c * 8192,
                     wm, wn3, lane);
    __syncthreads();

    {
        float* a3 = (float*)(sm + M2_OFF_A);
        const int r0 = wm + (lane >> 2);
        const int c0 = wn3 + (lane & 3) * 2;
        #pragma unroll
        for (int mt = 0; mt < 2; mt++) {
            #pragma unroll
            for (int nt = 0; nt < 2; nt++) {
                const int n = c0 + nt * 8;
                const float b0v = sb3[n], b1v = sb3[n + 1];
                float v;
                v = C3[mt][nt][0] + b0v; a3[(r0 + mt * 16) * 68 + n]     = v - tanhf(v);
                v = C3[mt][nt][1] + b1v; a3[(r0 + mt * 16) * 68 + n + 1] = v - tanhf(v);
                v = C3[mt][nt][2] + b0v; a3[(r0 + mt * 16 + 8) * 68 + n]     = v - tanhf(v);
                v = C3[mt][nt][3] + b1v; a3[(r0 + mt * 16 + 8) * 68 + n + 1] = v - tanhf(v);
            }
        }
    }
    __syncthreads();

    if (tid < 128) {
        const float* a3 = (const float*)(sm + M2_OFF_A);
        const int row = tid >> 1;
        const int c = tid & 1;
        float s = sb4[c];
        #pragma unroll
        for (int k = 0; k < 64; k++) s += a3[row * 68 + k] * sW4[k * 2 + c];
        out[(size_t)(b0 + row) * 2 + c] = 1.f / (1.f + expf(-s));
    }
}

// ---------------- launch ----------------
extern "C" void kernel_launch(void* const* d_in, const int* in_sizes, int n_in,
                              void* d_out, int out_size) {
    const float* x    = (const float*)d_in[0];
    const int*   apps = (const int*)d_in[1];
    const int*   es   = (const int*)d_in[2];
    const int*   ed   = (const int*)d_in[3];
    const float* emb  = (const float*)d_in[4];
    const float* gcw  = (const float*)d_in[5];
    const float* gcb  = (const float*)d_in[6];
    const float* W1   = (const float*)d_in[7];
    const float* b1   = (const float*)d_in[8];
    const float* W2   = (const float*)d_in[9];
    const float* b2   = (const float*)d_in[10];
    const float* W3   = (const float*)d_in[11];
    const float* b3   = (const float*)d_in[12];
    const float* W4   = (const float*)d_in[13];
    const float* b4   = (const float*)d_in[14];
    float* out = (float*)d_out;

    cudaFuncSetAttribute(gemm1_kernel, cudaFuncAttributeMaxDynamicSharedMemorySize, G1_SMEM);
    cudaFuncSetAttribute(mlp2_kernel, cudaFuncAttributeMaxDynamicSharedMemorySize, M2_SMEM);

    prep_kernel<<<512, 256>>>(es, ed, emb, gcw, gcb, W1, W2, W3);
    gconv_kernel<<<B_TOTAL / GC_ROWS, 256>>>(apps);
    gemm1_kernel<<<B_TOTAL / 128, 256, G1_SMEM>>>(x, b1);
    mlp2_kernel<<<B_TOTAL / 64, 256, M2_SMEM>>>(b2, b3, b4, W4, out);
}

// round 7
// speedup vs baseline: 1.3932x; 1.3932x over previous
#include <cuda_runtime.h>
#include <cuda_fp16.h>
#include <cstdint>

#define B_TOTAL 16384
#define NNODES  200
#define NEDGES  800
#define XF      2600
#define FEATR   2800
#define FEATP   2816          // K padded to 44*64
#define NT1     (FEATP / 64)  // 44

// ---------------- device scratch ----------------
__device__ __align__(16) float g_gbuf[(size_t)B_TOTAL * NNODES];
__device__ __align__(16) float g_a1[(size_t)B_TOTAL * 128];
__device__ float g_norm_dst[NNODES];
__device__ float g_ew[3];
__device__ float g_gcb;
__device__ int   g_csr_off[NNODES + 1];
__device__ int   g_csr_src[NEDGES];
__device__ float g_csr_w[NEDGES];
__device__ __align__(16) __half g_w1t[128 * FEATP];   // fp16, transposed [n][k]
__device__ __align__(16) __half g_w2t[128 * 128];
__device__ __align__(16) __half g_w3t[64 * 128];

// ---------------- helpers ----------------
__device__ __forceinline__ uint32_t smem_to_u32(const void* p) {
    uint32_t a;
    asm("{ .reg .u64 t; cvta.to.shared.u64 t, %1; cvt.u32.u64 %0, t; }" : "=r"(a) : "l"(p));
    return a;
}
#define SWZ(off) ((off) ^ (((off) >> 3) & 0x70))

__device__ __forceinline__ void ldsm4(uint32_t r[4], uint32_t addr) {
    asm volatile("ldmatrix.sync.aligned.m8n8.x4.shared.b16 {%0,%1,%2,%3}, [%4];"
                 : "=r"(r[0]), "=r"(r[1]), "=r"(r[2]), "=r"(r[3]) : "r"(addr));
}
__device__ __forceinline__ void mma16816h(float c[4], const uint32_t a[4],
                                          uint32_t b0, uint32_t b1) {
    asm volatile("mma.sync.aligned.m16n8k16.row.col.f32.f16.f16.f32 "
                 "{%0,%1,%2,%3}, {%4,%5,%6,%7}, {%8,%9}, {%0,%1,%2,%3};"
                 : "+f"(c[0]), "+f"(c[1]), "+f"(c[2]), "+f"(c[3])
                 : "r"(a[0]), "r"(a[1]), "r"(a[2]), "r"(a[3]), "r"(b0), "r"(b1));
}
__device__ __forceinline__ void cpa16(uint32_t dst, const void* src) {
    asm volatile("cp.async.cg.shared.global [%0], [%1], 16;" :: "r"(dst), "l"(src));
}
#define CPA_COMMIT() asm volatile("cp.async.commit_group;" ::: "memory")
#define CPA_WAIT0()  asm volatile("cp.async.wait_group 0;" ::: "memory")
#define CPA_WAIT1()  asm volatile("cp.async.wait_group 1;" ::: "memory")

// fp16 split: hi = rn(f16), lo = rn(residual). 22-bit combined accuracy.
__device__ __forceinline__ void split2h(float a, float b, uint32_t& hi2, uint32_t& lo2) {
    __half2 h = __floats2half2_rn(a, b);             // low = a, high = b
    hi2 = *reinterpret_cast<uint32_t*>(&h);
    float ar = a - __low2float(h);
    float br = b - __high2float(h);
    __half2 l = __floats2half2_rn(ar, br);
    lo2 = *reinterpret_cast<uint32_t*>(&l);
}
__device__ __forceinline__ float softplusf(float x) {
    return fmaxf(x, 0.f) + log1pf(expf(-fabsf(x)));
}

// ---------------- MMA chunk, 2-product fp16: warp tile 32 x (NTILES*8), K=64 ----------------
template<int NTILES>
__device__ __forceinline__ void mma_chunk2(float (&C)[2][NTILES][4],
                                           uint32_t a_hi, uint32_t a_lo, uint32_t b_u,
                                           int wm_base, int wn_base, int lane) {
    const int lr = (lane & 7) + ((lane >> 3) & 1) * 8;
    const int lh = (lane >> 4) * 16;
    #pragma unroll
    for (int kk = 0; kk < 4; kk++) {
        uint32_t ah[2][4], al[2][4];
        #pragma unroll
        for (int mt = 0; mt < 2; mt++) {
            uint32_t off = SWZ((uint32_t)((wm_base + mt * 16 + lr) * 128 + kk * 32 + lh));
            ldsm4(ah[mt], a_hi + off);
            ldsm4(al[mt], a_lo + off);
        }
        #pragma unroll
        for (int ng = 0; ng < NTILES / 2; ng++) {
            uint32_t off = SWZ((uint32_t)((wn_base + ng * 16 + lr) * 128 + kk * 32 + lh));
            uint32_t b[4];
            ldsm4(b, b_u + off);
            #pragma unroll
            for (int half = 0; half < 2; half++) {
                const int nt = ng * 2 + half;
                #pragma unroll
                for (int mt = 0; mt < 2; mt++) {
                    mma16816h(C[mt][nt], ah[mt], b[half], b[half + 2]);
                    mma16816h(C[mt][nt], al[mt], b[half], b[half + 2]);
                }
            }
        }
    }
}

// ---------------- prep: graph (block 0) + weight transpose to fp16 (all) ----------------
__global__ void prep_kernel(const int* __restrict__ es, const int* __restrict__ ed,
                            const float* __restrict__ emb, const float* __restrict__ gcw,
                            const float* __restrict__ gcb,
                            const float* __restrict__ W1, const float* __restrict__ W2,
                            const float* __restrict__ W3) {
    const int tid = threadIdx.x;
    if (blockIdx.x == 0) {
        __shared__ int cnto[NNODES], cnti[NNODES], pos[NNODES];
        for (int n = tid; n < NNODES; n += 256) { cnto[n] = 0; cnti[n] = 0; }
        __syncthreads();
        for (int e = tid; e < NEDGES; e += 256) {
            atomicAdd(&cnto[es[e]], 1);
            atomicAdd(&cnti[ed[e]], 1);
        }
        __syncthreads();
        for (int n = tid; n < NNODES; n += 256)
            g_norm_dst[n] = rsqrtf((float)max(cnti[n], 1));
        if (tid < 3) {
            float s = 0.f;
            #pragma unroll
            for (int j = 0; j < 5; j++) s += emb[tid * 5 + j] * gcw[j];
            g_ew[tid] = s;
        }
        if (tid == 0) {
            g_gcb = gcb[0];
            int off = 0;
            for (int d = 0; d < NNODES; d++) { g_csr_off[d] = off; pos[d] = off; off += cnti[d]; }
            g_csr_off[NNODES] = off;
        }
        __syncthreads();
        for (int e = tid; e < NEDGES; e += 256) {
            int d = ed[e], s = es[e];
            int p = atomicAdd(&pos[d], 1);
            g_csr_src[p] = s;
            g_csr_w[p] = rsqrtf((float)max(cnto[s], 1));
        }
    }
    const int T1 = 128 * FEATP, T2 = 128 * 128, T3 = 64 * 128;
    for (int i = blockIdx.x * blockDim.x + tid; i < T1 + T2 + T3;
         i += gridDim.x * blockDim.x) {
        float v;
        __half* ph;
        if (i < T1) {
            int k = i % FEATP;
            int n = i / FEATP;
            v = (k < FEATR) ? W1[(size_t)k * 128 + n] : 0.f;
            ph = g_w1t + i;
        } else if (i < T1 + T2) {
            int j = i - T1;
            int n = j >> 7, k = j & 127;
            v = W2[k * 128 + n];
            ph = g_w2t + j;
        } else {
            int j = i - T1 - T2;
            int n = j >> 7, k = j & 127;
            v = W3[k * 64 + n];
            ph = g_w3t + j;
        }
        *ph = __float2half_rn(v);
    }
}

#define GC_ROWS 8
__global__ __launch_bounds__(256) void gconv_kernel(const int* __restrict__ apps) {
    __shared__ float hw[GC_ROWS][NNODES];
    const int b0 = blockIdx.x * GC_ROWS;
    const int tid = threadIdx.x;
    for (int i = tid; i < GC_ROWS * NNODES; i += 256) {
        int r = i / NNODES, n = i % NNODES;
        hw[r][n] = g_ew[apps[(size_t)(b0 + r) * NNODES + n]];
    }
    __syncthreads();
    const float gcb = g_gcb;
    for (int i = tid; i < GC_ROWS * NNODES; i += 256) {
        int r = i / NNODES, d = i % NNODES;
        int o0 = g_csr_off[d], o1 = g_csr_off[d + 1];
        float s = 0.f;
        for (int e = o0; e < o1; e++) s += g_csr_w[e] * hw[r][g_csr_src[e]];
        g_gbuf[(size_t)(b0 + r) * NNODES + d] = g_norm_dst[d] * s + gcb;
    }
}

// ================= GEMM1: a1 = softplus(feat @ W1 + b1) =================
// 256 threads, BM=64, BN=128, 2 CTAs/SM, 3-stage B + 2-stage A pipeline.
#define G1_OFF_B1 0
#define G1_OFF_A  1024                   // 2 stages x (hi 8K + lo 8K) = 32KB
#define G1_OFF_BW (1024 + 32768)         // 3 stages x 16KB = 48KB
#define G1_SMEM   (1024 + 32768 + 49152)

// A chunk load: each thread owns row = tid>>2 (0..63), 16 k-floats at kq0 = (tid&3)*16
__device__ __forceinline__ void g1_lda(float4 (&pf)[4], const float* __restrict__ xr,
                                       const float* __restrict__ gr, int k0, int kq0) {
    if (k0 + 63 < XF) {
        #pragma unroll
        for (int j = 0; j < 4; j++) pf[j] = *(const float4*)(xr + k0 + kq0 + j * 4);
    } else {
        #pragma unroll
        for (int j = 0; j < 4; j++) {
            const int k = k0 + kq0 + j * 4;
            if (k + 3 < XF)       pf[j] = *(const float4*)(xr + k);
            else if (k < FEATR)   pf[j] = *(const float4*)(gr + (k - XF));
            else                  pf[j] = make_float4(0.f, 0.f, 0.f, 0.f);
        }
    }
}
// convert + store: 16 floats -> 2x uint4 hi + 2x uint4 lo (swizzled)
__device__ __forceinline__ void g1_sta(const float4 (&pf)[4], char* Ah, char* Al,
                                       int row, int kq0) {
    #pragma unroll
    for (int q = 0; q < 2; q++) {
        const float4 f0 = pf[q * 2], f1 = pf[q * 2 + 1];
        uint4 h, l;
        split2h(f0.x, f0.y, h.x, l.x);
        split2h(f0.z, f0.w, h.y, l.y);
        split2h(f1.x, f1.y, h.z, l.z);
        split2h(f1.z, f1.w, h.w, l.w);
        const uint32_t off = SWZ((uint32_t)(row * 128 + (kq0 + q * 8) * 2));
        *(uint4*)(Ah + off) = h;
        *(uint4*)(Al + off) = l;
    }
}

__global__ __launch_bounds__(256, 2)
void gemm1_kernel(const float* __restrict__ x, const float* __restrict__ b1g) {
    extern __shared__ char sm[];
    const uint32_t su = smem_to_u32(sm);
    const int tid = threadIdx.x;
    const int wid = tid >> 5;
    const int lane = tid & 31;
    const int b0 = blockIdx.x * 64;

    float* sb1 = (float*)(sm + G1_OFF_B1);
    if (tid < 128) sb1[tid] = b1g[tid];

    // A stages: hi0@0, lo0@8K, hi1@16K, lo1@24K
    char* pAh[2] = { sm + G1_OFF_A,          sm + G1_OFF_A + 16384 };
    char* pAl[2] = { sm + G1_OFF_A + 8192,   sm + G1_OFF_A + 24576 };
    const uint32_t uAh[2] = { su + G1_OFF_A,         su + G1_OFF_A + 16384 };
    const uint32_t uAl[2] = { su + G1_OFF_A + 8192,  su + G1_OFF_A + 24576 };
    // B stages (3 x 16KB)
    uint32_t uB[3];
    #pragma unroll
    for (int s = 0; s < 3; s++) uB[s] = su + G1_OFF_BW + s * 16384;

    const int arow = tid >> 2;
    const int kq0  = (tid & 3) * 16;
    const float* xr = x + (size_t)(b0 + arow) * XF;
    const float* gr = g_gbuf + (size_t)(b0 + arow) * NNODES;

    // B loader: 4 vec16 per tile per thread (1024 vec / 256 thr)
    uint32_t bofs[4];
    const __half* gw[4];
    #pragma unroll
    for (int i = 0; i < 4; i++) {
        const int v = tid + i * 256;
        bofs[i] = SWZ((uint32_t)((v >> 3) * 128 + (v & 7) * 16));
        gw[i] = g_w1t + (size_t)(v >> 3) * FEATP + (v & 7) * 8;
    }

    const int wm = (wid >> 2) * 32;   // 2 M-groups of 32
    const int wn = (wid & 3) * 32;    // 4 N-groups of 32

    float C[2][4][4];
    #pragma unroll
    for (int i = 0; i < 2; i++)
        #pragma unroll
        for (int j = 0; j < 4; j++)
            #pragma unroll
            for (int q = 0; q < 4; q++) C[i][j][q] = 0.f;

    float4 pf[4];
    // ---- prologue ----
    #pragma unroll
    for (int i = 0; i < 4; i++) cpa16(uB[0] + bofs[i], gw[i]);
    CPA_COMMIT();
    #pragma unroll
    for (int i = 0; i < 4; i++) cpa16(uB[1] + bofs[i], gw[i] + 64);
    CPA_COMMIT();
    g1_lda(pf, xr, gr, 0, kq0);
    g1_sta(pf, pAh[0], pAl[0], arow, kq0);
    g1_lda(pf, xr, gr, 64, kq0);
    CPA_WAIT1();          // B stage 0 ready
    __syncthreads();

    // ---- mainloop ----
    for (int t = 0; t < NT1; t++) {
        const int cur = t & 1;
        const int bs = t - (t / 3) * 3;
        const bool more2 = (t + 2 < NT1);
        if (more2) {
            const int koff = (t + 2) * 64;
            const int ns = (t + 2) - ((t + 2) / 3) * 3;
            #pragma unroll
            for (int i = 0; i < 4; i++) cpa16(uB[ns] + bofs[i], gw[i] + koff);
            CPA_COMMIT();
        }
        if (t + 1 < NT1)
            g1_sta(pf, pAh[cur ^ 1], pAl[cur ^ 1], arow, kq0);   // store chunk t+1
        if (more2)
            g1_lda(pf, xr, gr, (t + 2) * 64, kq0);               // load chunk t+2
        mma_chunk2<4>(C, uAh[cur], uAl[cur], uB[bs], wm, wn, lane);
        if (more2) CPA_WAIT1(); else CPA_WAIT0();
        __syncthreads();
    }

    // ---- epilogue: bias + softplus -> g_a1 (f32) ----
    {
        const int r0 = wm + (lane >> 2);
        const int c0 = wn + (lane & 3) * 2;
        #pragma unroll
        for (int mt = 0; mt < 2; mt++) {
            #pragma unroll
            for (int nt = 0; nt < 4; nt++) {
                const int c = c0 + nt * 8;
                const float bb0 = sb1[c], bb1 = sb1[c + 1];
                float2 v01 = make_float2(softplusf(C[mt][nt][0] + bb0),
                                         softplusf(C[mt][nt][1] + bb1));
                float2 v23 = make_float2(softplusf(C[mt][nt][2] + bb0),
                                         softplusf(C[mt][nt][3] + bb1));
                *(float2*)(g_a1 + (size_t)(b0 + r0 + mt * 16) * 128 + c) = v01;
                *(float2*)(g_a1 + (size_t)(b0 + r0 + mt * 16 + 8) * 128 + c) = v23;
            }
        }
    }
}

// ================= kernel 2: layers 2-4 =================
// BM=64, 256 threads, 2 CTAs/SM, grid 256.
#define M2_OFF_B2 0
#define M2_OFF_B3 512
#define M2_OFF_B4 768
#define M2_OFF_W4 1024
#define M2_OFF_A  2048                    // a tiles: hi[2] @ +0,+8K ; lo[2] @ +16K,+24K (32KB)
#define M2_OFF_BW (2048 + 32768)          // W tiles: 2 x 16KB (W2) / 2 x 8KB (W3)
#define M2_SMEM   (2048 + 32768 + 32768)

__device__ __forceinline__ void m2_cpa_W(const __half* __restrict__ W, int ldk,
                                         int k0, uint32_t dst, int nrows, int tid) {
    const int nv = nrows * 8;
    for (int v = tid; v < nv; v += 256) {
        const int n = v >> 3, kq = (v & 7) * 8;
        cpa16(dst + SWZ((uint32_t)(n * 128 + kq * 2)), W + (size_t)n * ldk + k0 + kq);
    }
}

__device__ __forceinline__ void m2_epi_split(float (&C)[2][4][4], const float* bias,
                                             char* dhi, char* dlo,
                                             int wm_base, int wn_base, int lane) {
    const int r0 = wm_base + (lane >> 2);
    const int c0 = wn_base + (lane & 3) * 2;
    #pragma unroll
    for (int mt = 0; mt < 2; mt++) {
        #pragma unroll
        for (int nt = 0; nt < 4; nt++) {
            const int n = c0 + nt * 8;
            const int chunk = n >> 6, col = n & 63;
            const float b0 = bias[n], b1 = bias[n + 1];
            char* th = dhi + chunk * 8192;
            char* tl = dlo + chunk * 8192;
            {
                float v0 = softplusf(C[mt][nt][0] + b0);
                float v1 = softplusf(C[mt][nt][1] + b1);
                uint32_t h, l;
                split2h(v0, v1, h, l);
                const uint32_t off = SWZ((uint32_t)((r0 + mt * 16) * 128 + col * 2));
                *(uint32_t*)(th + off) = h;
                *(uint32_t*)(tl + off) = l;
            }
            {
                float v0 = softplusf(C[mt][nt][2] + b0);
                float v1 = softplusf(C[mt][nt][3] + b1);
                uint32_t h, l;
                split2h(v0, v1, h, l);
                const uint32_t off = SWZ((uint32_t)((r0 + mt * 16 + 8) * 128 + col * 2));
                *(uint32_t*)(th + off) = h;
                *(uint32_t*)(tl + off) = l;
            }
        }
    }
}

__global__ __launch_bounds__(256, 2)
void mlp2_kernel(const float* __restrict__ b2g, const float* __restrict__ b3g,
                 const float* __restrict__ b4g, const float* __restrict__ W4g,
                 float* __restrict__ out) {
    extern __shared__ char sm[];
    const uint32_t su = smem_to_u32(sm);
    const int tid = threadIdx.x;
    const int wid = tid >> 5;
    const int lane = tid & 31;
    const int b0 = blockIdx.x * 64;

    float* sb2 = (float*)(sm + M2_OFF_B2);
    float* sb3 = (float*)(sm + M2_OFF_B3);
    float* sb4 = (float*)(sm + M2_OFF_B4);
    float* sW4 = (float*)(sm + M2_OFF_W4);
    if (tid < 128) { sb2[tid] = b2g[tid]; sW4[tid] = W4g[tid]; }
    if (tid < 64) sb3[tid] = b3g[tid];
    if (tid < 2) sb4[tid] = b4g[tid];

    char* pAh[2] = { sm + M2_OFF_A,          sm + M2_OFF_A + 8192 };
    char* pAl[2] = { sm + M2_OFF_A + 16384,  sm + M2_OFF_A + 24576 };
    const uint32_t uAh[2] = { su + M2_OFF_A,         su + M2_OFF_A + 8192 };
    const uint32_t uAl[2] = { su + M2_OFF_A + 16384, su + M2_OFF_A + 24576 };
    const uint32_t uB[2]  = { su + M2_OFF_BW,        su + M2_OFF_BW + 16384 };

    // W2 tiles early
    m2_cpa_W(g_w2t, 128, 0,  uB[0], 128, tid);
    m2_cpa_W(g_w2t, 128, 64, uB[1], 128, tid);
    CPA_COMMIT();

    // load a1 (f32) + split into A tiles
    {
        const int row = tid >> 2;
        const int kq0 = (tid & 3) * 16;
        const float* ar = g_a1 + (size_t)(b0 + row) * 128;
        #pragma unroll
        for (int c = 0; c < 2; c++) {
            #pragma unroll
            for (int j = 0; j < 4; j++) {
                const int kl = kq0 + j * 4;
                float4 f = *(const float4*)(ar + c * 64 + kl);
                uint32_t h01, l01, h23, l23;
                split2h(f.x, f.y, h01, l01);
                split2h(f.z, f.w, h23, l23);
                const uint32_t off = SWZ((uint32_t)(row * 128 + kl * 2));
                *(uint2*)(pAh[c] + off) = make_uint2(h01, h23);
                *(uint2*)(pAl[c] + off) = make_uint2(l01, l23);
            }
        }
    }
    CPA_WAIT0();
    __syncthreads();

    const int wm = (wid >> 2) * 32;
    const int wn = (wid & 3) * 32;

    // GEMM2
    float C[2][4][4];
    #pragma unroll
    for (int i = 0; i < 2; i++)
        #pragma unroll
        for (int j = 0; j < 4; j++)
            #pragma unroll
            for (int q = 0; q < 4; q++) C[i][j][q] = 0.f;
    #pragma unroll
    for (int c = 0; c < 2; c++)
        mma_chunk2<4>(C, uAh[c], uAl[c], uB[c], wm, wn, lane);
    __syncthreads();

    // epi2 -> a2 tiles (overwrite a1); W3 tiles (8KB each)
    m2_epi_split(C, sb2, sm + M2_OFF_A, sm + M2_OFF_A + 16384, wm, wn, lane);
    m2_cpa_W(g_w3t, 128, 0,  su + M2_OFF_BW,        64, tid);
    m2_cpa_W(g_w3t, 128, 64, su + M2_OFF_BW + 8192, 64, tid);
    CPA_COMMIT();
    CPA_WAIT0();
    __syncthreads();

    // GEMM3 (N=64), warp tile 32x16
    const int wn3 = (wid & 3) * 16;
    float C3[2][2][4];
    #pragma unroll
    for (int i = 0; i < 2; i++)
        #pragma unroll
        for (int j = 0; j < 2; j++)
            #pragma unroll
            for (int q = 0; q < 4; q++) C3[i][j][q] = 0.f;
    #pragma unroll
    for (int c = 0; c < 2; c++)
        mma_chunk2<2>(C3, uAh[c], uAl[c], su + M2_OFF_BW + c * 8192, wm, wn3, lane);
    __syncthreads();

    // epi3: tanhshrink -> a3 fp32 [64][68]
    {
        float* a3 = (float*)(sm + M2_OFF_A);
        const int r0 = wm + (lane >> 2);
        const int c0 = wn3 + (lane & 3) * 2;
        #pragma unroll
        for (int mt = 0; mt < 2; mt++) {
            #pragma unroll
            for (int nt = 0; nt < 2; nt++) {
                const int n = c0 + nt * 8;
                const float b0v = sb3[n], b1v = sb3[n + 1];
                float v;
                v = C3[mt][nt][0] + b0v; a3[(r0 + mt * 16) * 68 + n]     = v - tanhf(v);
                v = C3[mt][nt][1] + b1v; a3[(r0 + mt * 16) * 68 + n + 1] = v - tanhf(v);
                v = C3[mt][nt][2] + b0v; a3[(r0 + mt * 16 + 8) * 68 + n]     = v - tanhf(v);
                v = C3[mt][nt][3] + b1v; a3[(r0 + mt * 16 + 8) * 68 + n + 1] = v - tanhf(v);
            }
        }
    }
    __syncthreads();

    // layer 4 + sigmoid
    if (tid < 128) {
        const float* a3 = (const float*)(sm + M2_OFF_A);
        const int row = tid >> 1;
        const int c = tid & 1;
        float s = sb4[c];
        #pragma unroll
        for (int k = 0; k < 64; k++) s += a3[row * 68 + k] * sW4[k * 2 + c];
        out[(size_t)(b0 + row) * 2 + c] = 1.f / (1.f + expf(-s));
    }
}

// ---------------- launch ----------------
extern "C" void kernel_launch(void* const* d_in, const int* in_sizes, int n_in,
                              void* d_out, int out_size) {
    const float* x    = (const float*)d_in[0];
    const int*   apps = (const int*)d_in[1];
    const int*   es   = (const int*)d_in[2];
    const int*   ed   = (const int*)d_in[3];
    const float* emb  = (const float*)d_in[4];
    const float* gcw  = (const float*)d_in[5];
    const float* gcb  = (const float*)d_in[6];
    const float* W1   = (const float*)d_in[7];
    const float* b1   = (const float*)d_in[8];
    const float* W2   = (const float*)d_in[9];
    const float* b2   = (const float*)d_in[10];
    const float* W3   = (const float*)d_in[11];
    const float* b3   = (const float*)d_in[12];
    const float* W4   = (const float*)d_in[13];
    const float* b4   = (const float*)d_in[14];
    float* out = (float*)d_out;

    cudaFuncSetAttribute(gemm1_kernel, cudaFuncAttributeMaxDynamicSharedMemorySize, G1_SMEM);
    cudaFuncSetAttribute(mlp2_kernel, cudaFuncAttributeMaxDynamicSharedMemorySize, M2_SMEM);

    prep_kernel<<<512, 256>>>(es, ed, emb, gcw, gcb, W1, W2, W3);
    gconv_kernel<<<B_TOTAL / GC_ROWS, 256>>>(apps);
    gemm1_kernel<<<B_TOTAL / 64, 256, G1_SMEM>>>(x, b1);
    mlp2_kernel<<<B_TOTAL / 64, 256, M2_SMEM>>>(b2, b3, b4, W4, out);
}

// round 8
// speedup vs baseline: 1.7503x; 1.2563x over previous
#include <cuda_runtime.h>
#include <cuda_fp16.h>
#include <cstdint>

#define B_TOTAL 16384
#define NNODES  200
#define NEDGES  800
#define XF      2600
#define FEATR   2800
#define FEATP   2816          // K padded to 44*64
#define NT1     (FEATP / 64)  // 44

// ---------------- device scratch ----------------
__device__ __align__(16) float g_gbuf[(size_t)B_TOTAL * NNODES];
__device__ __align__(16) __half g_a1h[(size_t)B_TOTAL * 128];
__device__ float g_norm_dst[NNODES];
__device__ float g_ew[3];
__device__ float g_gcb;
__device__ int   g_csr_off[NNODES + 1];
__device__ int   g_csr_src[NEDGES];
__device__ float g_csr_w[NEDGES];
__device__ __align__(16) __half g_w1t[128 * FEATP];   // fp16, transposed [n][k]
__device__ __align__(16) __half g_w2t[128 * 128];
__device__ __align__(16) __half g_w3t[64 * 128];

// ---------------- helpers ----------------
__device__ __forceinline__ uint32_t smem_to_u32(const void* p) {
    uint32_t a;
    asm("{ .reg .u64 t; cvta.to.shared.u64 t, %1; cvt.u32.u64 %0, t; }" : "=r"(a) : "l"(p));
    return a;
}
#define SWZ(off) ((off) ^ (((off) >> 3) & 0x70))

__device__ __forceinline__ void ldsm4(uint32_t r[4], uint32_t addr) {
    asm volatile("ldmatrix.sync.aligned.m8n8.x4.shared.b16 {%0,%1,%2,%3}, [%4];"
                 : "=r"(r[0]), "=r"(r[1]), "=r"(r[2]), "=r"(r[3]) : "r"(addr));
}
__device__ __forceinline__ void mma16816h(float c[4], const uint32_t a[4],
                                          uint32_t b0, uint32_t b1) {
    asm volatile("mma.sync.aligned.m16n8k16.row.col.f32.f16.f16.f32 "
                 "{%0,%1,%2,%3}, {%4,%5,%6,%7}, {%8,%9}, {%0,%1,%2,%3};"
                 : "+f"(c[0]), "+f"(c[1]), "+f"(c[2]), "+f"(c[3])
                 : "r"(a[0]), "r"(a[1]), "r"(a[2]), "r"(a[3]), "r"(b0), "r"(b1));
}
__device__ __forceinline__ void cpa16(uint32_t dst, const void* src) {
    asm volatile("cp.async.cg.shared.global [%0], [%1], 16;" :: "r"(dst), "l"(src));
}
#define CPA_COMMIT() asm volatile("cp.async.commit_group;" ::: "memory")
#define CPA_WAIT0()  asm volatile("cp.async.wait_group 0;" ::: "memory")
#define CPA_WAIT1()  asm volatile("cp.async.wait_group 1;" ::: "memory")

__device__ __forceinline__ uint32_t packh2(float a, float b) {
    __half2 h = __floats2half2_rn(a, b);
    return *reinterpret_cast<uint32_t*>(&h);
}
__device__ __forceinline__ float softplusf(float x) {
    return fmaxf(x, 0.f) + log1pf(expf(-fabsf(x)));
}

// ---------------- MMA chunk, single-product fp16: warp tile 32 x (NTILES*8), K=64 ----------------
template<int NTILES>
__device__ __forceinline__ void mma_chunk1(float (&C)[2][NTILES][4],
                                           uint32_t a_u, uint32_t b_u,
                                           int wm_base, int wn_base, int lane) {
    const int lr = (lane & 7) + ((lane >> 3) & 1) * 8;
    const int lh = (lane >> 4) * 16;
    #pragma unroll
    for (int kk = 0; kk < 4; kk++) {
        uint32_t a[2][4];
        #pragma unroll
        for (int mt = 0; mt < 2; mt++) {
            uint32_t off = SWZ((uint32_t)((wm_base + mt * 16 + lr) * 128 + kk * 32 + lh));
            ldsm4(a[mt], a_u + off);
        }
        #pragma unroll
        for (int ng = 0; ng < NTILES / 2; ng++) {
            uint32_t off = SWZ((uint32_t)((wn_base + ng * 16 + lr) * 128 + kk * 32 + lh));
            uint32_t b[4];
            ldsm4(b, b_u + off);
            #pragma unroll
            for (int half = 0; half < 2; half++) {
                const int nt = ng * 2 + half;
                #pragma unroll
                for (int mt = 0; mt < 2; mt++)
                    mma16816h(C[mt][nt], a[mt], b[half], b[half + 2]);
            }
        }
    }
}

// ---------------- prep: graph (block 0) + weight transpose to fp16 (all) ----------------
__global__ void prep_kernel(const int* __restrict__ es, const int* __restrict__ ed,
                            const float* __restrict__ emb, const float* __restrict__ gcw,
                            const float* __restrict__ gcb,
                            const float* __restrict__ W1, const float* __restrict__ W2,
                            const float* __restrict__ W3) {
    const int tid = threadIdx.x;
    if (blockIdx.x == 0) {
        __shared__ int cnto[NNODES], cnti[NNODES], pos[NNODES];
        for (int n = tid; n < NNODES; n += 256) { cnto[n] = 0; cnti[n] = 0; }
        __syncthreads();
        for (int e = tid; e < NEDGES; e += 256) {
            atomicAdd(&cnto[es[e]], 1);
            atomicAdd(&cnti[ed[e]], 1);
        }
        __syncthreads();
        for (int n = tid; n < NNODES; n += 256)
            g_norm_dst[n] = rsqrtf((float)max(cnti[n], 1));
        if (tid < 3) {
            float s = 0.f;
            #pragma unroll
            for (int j = 0; j < 5; j++) s += emb[tid * 5 + j] * gcw[j];
            g_ew[tid] = s;
        }
        if (tid == 0) {
            g_gcb = gcb[0];
            int off = 0;
            for (int d = 0; d < NNODES; d++) { g_csr_off[d] = off; pos[d] = off; off += cnti[d]; }
            g_csr_off[NNODES] = off;
        }
        __syncthreads();
        for (int e = tid; e < NEDGES; e += 256) {
            int d = ed[e], s = es[e];
            int p = atomicAdd(&pos[d], 1);
            g_csr_src[p] = s;
            g_csr_w[p] = rsqrtf((float)max(cnto[s], 1));
        }
    }
    const int T1 = 128 * FEATP, T2 = 128 * 128, T3 = 64 * 128;
    for (int i = blockIdx.x * blockDim.x + tid; i < T1 + T2 + T3;
         i += gridDim.x * blockDim.x) {
        float v;
        __half* ph;
        if (i < T1) {
            int k = i % FEATP;
            int n = i / FEATP;
            v = (k < FEATR) ? W1[(size_t)k * 128 + n] : 0.f;
            ph = g_w1t + i;
        } else if (i < T1 + T2) {
            int j = i - T1;
            int n = j >> 7, k = j & 127;
            v = W2[k * 128 + n];
            ph = g_w2t + j;
        } else {
            int j = i - T1 - T2;
            int n = j >> 7, k = j & 127;
            v = W3[k * 64 + n];
            ph = g_w3t + j;
        }
        *ph = __float2half_rn(v);
    }
}

#define GC_ROWS 8
__global__ __launch_bounds__(256) void gconv_kernel(const int* __restrict__ apps) {
    __shared__ float hw[GC_ROWS][NNODES];
    const int b0 = blockIdx.x * GC_ROWS;
    const int tid = threadIdx.x;
    for (int i = tid; i < GC_ROWS * NNODES; i += 256) {
        int r = i / NNODES, n = i % NNODES;
        hw[r][n] = g_ew[apps[(size_t)(b0 + r) * NNODES + n]];
    }
    __syncthreads();
    const float gcb = g_gcb;
    for (int i = tid; i < GC_ROWS * NNODES; i += 256) {
        int r = i / NNODES, d = i % NNODES;
        int o0 = g_csr_off[d], o1 = g_csr_off[d + 1];
        float s = 0.f;
        for (int e = o0; e < o1; e++) s += g_csr_w[e] * hw[r][g_csr_src[e]];
        g_gbuf[(size_t)(b0 + r) * NNODES + d] = g_norm_dst[d] * s + gcb;
    }
}

// ================= GEMM1: a1 = softplus(feat @ W1 + b1) -> fp16 =================
// 256 threads, BM=64, BN=128, 2 CTAs/SM, 3-stage B + 2-ahead A pipeline, single fp16 product.
#define G1_OFF_B1 0
#define G1_OFF_A  1024                   // 2 stages x 8KB = 16KB
#define G1_OFF_BW (1024 + 16384)         // 3 stages x 16KB = 48KB
#define G1_SMEM   (1024 + 16384 + 49152)

__device__ __forceinline__ void g1_lda(float4 (&pf)[4], const float* __restrict__ xr,
                                       const float* __restrict__ gr, int k0, int kq0) {
    if (k0 + 63 < XF) {
        #pragma unroll
        for (int j = 0; j < 4; j++) pf[j] = *(const float4*)(xr + k0 + kq0 + j * 4);
    } else {
        #pragma unroll
        for (int j = 0; j < 4; j++) {
            const int k = k0 + kq0 + j * 4;
            if (k + 3 < XF)       pf[j] = *(const float4*)(xr + k);
            else if (k < FEATR)   pf[j] = *(const float4*)(gr + (k - XF));
            else                  pf[j] = make_float4(0.f, 0.f, 0.f, 0.f);
        }
    }
}
// convert + store: 16 floats -> 2x uint4 (fp16), swizzled
__device__ __forceinline__ void g1_sta(const float4 (&pf)[4], char* Ab, int row, int kq0) {
    #pragma unroll
    for (int q = 0; q < 2; q++) {
        const float4 f0 = pf[q * 2], f1 = pf[q * 2 + 1];
        uint4 h;
        h.x = packh2(f0.x, f0.y);
        h.y = packh2(f0.z, f0.w);
        h.z = packh2(f1.x, f1.y);
        h.w = packh2(f1.z, f1.w);
        const uint32_t off = SWZ((uint32_t)(row * 128 + (kq0 + q * 8) * 2));
        *(uint4*)(Ab + off) = h;
    }
}

__global__ __launch_bounds__(256, 2)
void gemm1_kernel(const float* __restrict__ x, const float* __restrict__ b1g) {
    extern __shared__ char sm[];
    const uint32_t su = smem_to_u32(sm);
    const int tid = threadIdx.x;
    const int wid = tid >> 5;
    const int lane = tid & 31;
    const int b0 = blockIdx.x * 64;

    float* sb1 = (float*)(sm + G1_OFF_B1);
    if (tid < 128) sb1[tid] = b1g[tid];

    char* pA[2] = { sm + G1_OFF_A, sm + G1_OFF_A + 8192 };
    const uint32_t uA[2] = { su + G1_OFF_A, su + G1_OFF_A + 8192 };
    uint32_t uB[3];
    #pragma unroll
    for (int s = 0; s < 3; s++) uB[s] = su + G1_OFF_BW + s * 16384;

    const int arow = tid >> 2;
    const int kq0  = (tid & 3) * 16;
    const float* xr = x + (size_t)(b0 + arow) * XF;
    const float* gr = g_gbuf + (size_t)(b0 + arow) * NNODES;

    uint32_t bofs[4];
    const __half* gw[4];
    #pragma unroll
    for (int i = 0; i < 4; i++) {
        const int v = tid + i * 256;
        bofs[i] = SWZ((uint32_t)((v >> 3) * 128 + (v & 7) * 16));
        gw[i] = g_w1t + (size_t)(v >> 3) * FEATP + (v & 7) * 8;
    }

    const int wm = (wid >> 2) * 32;   // 2 M-groups of 32
    const int wn = (wid & 3) * 32;    // 4 N-groups of 32

    float C[2][4][4];
    #pragma unroll
    for (int i = 0; i < 2; i++)
        #pragma unroll
        for (int j = 0; j < 4; j++)
            #pragma unroll
            for (int q = 0; q < 4; q++) C[i][j][q] = 0.f;

    float4 pf[4];
    // ---- prologue ----
    #pragma unroll
    for (int i = 0; i < 4; i++) cpa16(uB[0] + bofs[i], gw[i]);
    CPA_COMMIT();
    #pragma unroll
    for (int i = 0; i < 4; i++) cpa16(uB[1] + bofs[i], gw[i] + 64);
    CPA_COMMIT();
    g1_lda(pf, xr, gr, 0, kq0);
    g1_sta(pf, pA[0], arow, kq0);
    g1_lda(pf, xr, gr, 64, kq0);
    CPA_WAIT1();
    __syncthreads();

    // ---- mainloop ----
    for (int t = 0; t < NT1; t++) {
        const int cur = t & 1;
        const int bs = t - (t / 3) * 3;
        const bool more2 = (t + 2 < NT1);
        if (more2) {
            const int koff = (t + 2) * 64;
            const int ns = (t + 2) - ((t + 2) / 3) * 3;
            #pragma unroll
            for (int i = 0; i < 4; i++) cpa16(uB[ns] + bofs[i], gw[i] + koff);
            CPA_COMMIT();
        }
        if (t + 1 < NT1)
            g1_sta(pf, pA[cur ^ 1], arow, kq0);
        if (more2)
            g1_lda(pf, xr, gr, (t + 2) * 64, kq0);
        mma_chunk1<4>(C, uA[cur], uB[bs], wm, wn, lane);
        if (more2) CPA_WAIT1(); else CPA_WAIT0();
        __syncthreads();
    }

    // ---- epilogue: bias + softplus -> g_a1h (fp16) ----
    {
        const int r0 = wm + (lane >> 2);
        const int c0 = wn + (lane & 3) * 2;
        #pragma unroll
        for (int mt = 0; mt < 2; mt++) {
            #pragma unroll
            for (int nt = 0; nt < 4; nt++) {
                const int c = c0 + nt * 8;
                const float bb0 = sb1[c], bb1 = sb1[c + 1];
                uint32_t p01 = packh2(softplusf(C[mt][nt][0] + bb0),
                                      softplusf(C[mt][nt][1] + bb1));
                uint32_t p23 = packh2(softplusf(C[mt][nt][2] + bb0),
                                      softplusf(C[mt][nt][3] + bb1));
                *(uint32_t*)(g_a1h + (size_t)(b0 + r0 + mt * 16) * 128 + c) = p01;
                *(uint32_t*)(g_a1h + (size_t)(b0 + r0 + mt * 16 + 8) * 128 + c) = p23;
            }
        }
    }
}

// ================= kernel 2: layers 2-4 =================
// BM=64, 256 threads, 2 CTAs/SM, grid 256, single fp16 product.
#define M2_OFF_B2 0
#define M2_OFF_B3 512
#define M2_OFF_B4 768
#define M2_OFF_W4 1024
#define M2_OFF_A  2048                    // a tiles: 2 x 8KB
#define M2_OFF_BW (2048 + 16384)          // W tiles: 2 x 16KB (W2) / 2 x 8KB (W3)
#define M2_SMEM   (2048 + 16384 + 32768)

__device__ __forceinline__ void m2_cpa_W(const __half* __restrict__ W, int ldk,
                                         int k0, uint32_t dst, int nrows, int tid) {
    const int nv = nrows * 8;
    for (int v = tid; v < nv; v += 256) {
        const int n = v >> 3, kq = (v & 7) * 8;
        cpa16(dst + SWZ((uint32_t)(n * 128 + kq * 2)), W + (size_t)n * ldk + k0 + kq);
    }
}

// epilogue: bias + softplus -> fp16 chunked swizzled tiles
__device__ __forceinline__ void m2_epi(float (&C)[2][4][4], const float* bias,
                                       char* dst, int wm_base, int wn_base, int lane) {
    const int r0 = wm_base + (lane >> 2);
    const int c0 = wn_base + (lane & 3) * 2;
    #pragma unroll
    for (int mt = 0; mt < 2; mt++) {
        #pragma unroll
        for (int nt = 0; nt < 4; nt++) {
            const int n = c0 + nt * 8;
            const int chunk = n >> 6, col = n & 63;
            const float b0 = bias[n], b1 = bias[n + 1];
            char* td = dst + chunk * 8192;
            uint32_t p01 = packh2(softplusf(C[mt][nt][0] + b0),
                                  softplusf(C[mt][nt][1] + b1));
            uint32_t p23 = packh2(softplusf(C[mt][nt][2] + b0),
                                  softplusf(C[mt][nt][3] + b1));
            *(uint32_t*)(td + SWZ((uint32_t)((r0 + mt * 16) * 128 + col * 2))) = p01;
            *(uint32_t*)(td + SWZ((uint32_t)((r0 + mt * 16 + 8) * 128 + col * 2))) = p23;
        }
    }
}

__global__ __launch_bounds__(256, 2)
void mlp2_kernel(const float* __restrict__ b2g, const float* __restrict__ b3g,
                 const float* __restrict__ b4g, const float* __restrict__ W4g,
                 float* __restrict__ out) {
    extern __shared__ char sm[];
    const uint32_t su = smem_to_u32(sm);
    const int tid = threadIdx.x;
    const int wid = tid >> 5;
    const int lane = tid & 31;
    const int b0 = blockIdx.x * 64;

    float* sb2 = (float*)(sm + M2_OFF_B2);
    float* sb3 = (float*)(sm + M2_OFF_B3);
    float* sb4 = (float*)(sm + M2_OFF_B4);
    float* sW4 = (float*)(sm + M2_OFF_W4);
    if (tid < 128) { sb2[tid] = b2g[tid]; sW4[tid] = W4g[tid]; }
    if (tid < 64) sb3[tid] = b3g[tid];
    if (tid < 2) sb4[tid] = b4g[tid];

    const uint32_t uA[2] = { su + M2_OFF_A, su + M2_OFF_A + 8192 };
    const uint32_t uB[2] = { su + M2_OFF_BW, su + M2_OFF_BW + 16384 };

    // a1 (fp16) + W2 via cp.async
    m2_cpa_W(g_a1h + (size_t)b0 * 128, 128, 0,  uA[0], 64, tid);
    m2_cpa_W(g_a1h + (size_t)b0 * 128, 128, 64, uA[1], 64, tid);
    m2_cpa_W(g_w2t, 128, 0,  uB[0], 128, tid);
    m2_cpa_W(g_w2t, 128, 64, uB[1], 128, tid);
    CPA_COMMIT();
    CPA_WAIT0();
    __syncthreads();

    const int wm = (wid >> 2) * 32;
    const int wn = (wid & 3) * 32;

    // GEMM2
    float C[2][4][4];
    #pragma unroll
    for (int i = 0; i < 2; i++)
        #pragma unroll
        for (int j = 0; j < 4; j++)
            #pragma unroll
            for (int q = 0; q < 4; q++) C[i][j][q] = 0.f;
    #pragma unroll
    for (int c = 0; c < 2; c++)
        mma_chunk1<4>(C, uA[c], uB[c], wm, wn, lane);
    __syncthreads();

    // epi2 -> a2 tiles (overwrite a1 region); W3 tiles (8KB each)
    m2_epi(C, sb2, sm + M2_OFF_A, wm, wn, lane);
    m2_cpa_W(g_w3t, 128, 0,  su + M2_OFF_BW,        64, tid);
    m2_cpa_W(g_w3t, 128, 64, su + M2_OFF_BW + 8192, 64, tid);
    CPA_COMMIT();
    CPA_WAIT0();
    __syncthreads();

    // GEMM3 (N=64), warp tile 32x16
    const int wn3 = (wid & 3) * 16;
    float C3[2][2][4];
    #pragma unroll
    for (int i = 0; i < 2; i++)
        #pragma unroll
        for (int j = 0; j < 2; j++)
            #pragma unroll
            for (int q = 0; q < 4; q++) C3[i][j][q] = 0.f;
    #pragma unroll
    for (int c = 0; c < 2; c++)
        mma_chunk1<2>(C3, uA[c], su + M2_OFF_BW + c * 8192, wm, wn3, lane);
    __syncthreads();

    // epi3: tanhshrink -> a3 fp32 [64][68] (A region, now free)
    {
        float* a3 = (float*)(sm + M2_OFF_A);
        const int r0 = wm + (lane >> 2);
        const int c0 = wn3 + (lane & 3) * 2;
        #pragma unroll
        for (int mt = 0; mt < 2; mt++) {
            #pragma unroll
            for (int nt = 0; nt < 2; nt++) {
                const int n = c0 + nt * 8;
                const float b0v = sb3[n], b1v = sb3[n + 1];
                float v;
                v = C3[mt][nt][0] + b0v; a3[(r0 + mt * 16) * 68 + n]     = v - tanhf(v);
                v = C3[mt][nt][1] + b1v; a3[(r0 + mt * 16) * 68 + n + 1] = v - tanhf(v);
                v = C3[mt][nt][2] + b0v; a3[(r0 + mt * 16 + 8) * 68 + n]     = v - tanhf(v);
                v = C3[mt][nt][3] + b1v; a3[(r0 + mt * 16 + 8) * 68 + n + 1] = v - tanhf(v);
            }
        }
    }
    __syncthreads();

    // layer 4 + sigmoid
    if (tid < 128) {
        const float* a3 = (const float*)(sm + M2_OFF_A);
        const int row = tid >> 1;
        const int c = tid & 1;
        float s = sb4[c];
        #pragma unroll
        for (int k = 0; k < 64; k++) s += a3[row * 68 + k] * sW4[k * 2 + c];
        out[(size_t)(b0 + row) * 2 + c] = 1.f / (1.f + expf(-s));
    }
}

// ---------------- launch ----------------
extern "C" void kernel_launch(void* const* d_in, const int* in_sizes, int n_in,
                              void* d_out, int out_size) {
    const float* x    = (const float*)d_in[0];
    const int*   apps = (const int*)d_in[1];
    const int*   es   = (const int*)d_in[2];
    const int*   ed   = (const int*)d_in[3];
    const float* emb  = (const float*)d_in[4];
    const float* gcw  = (const float*)d_in[5];
    const float* gcb  = (const float*)d_in[6];
    const float* W1   = (const float*)d_in[7];
    const float* b1   = (const float*)d_in[8];
    const float* W2   = (const float*)d_in[9];
    const float* b2   = (const float*)d_in[10];
    const float* W3   = (const float*)d_in[11];
    const float* b3   = (const float*)d_in[12];
    const float* W4   = (const float*)d_in[13];
    const float* b4   = (const float*)d_in[14];
    float* out = (float*)d_out;

    cudaFuncSetAttribute(gemm1_kernel, cudaFuncAttributeMaxDynamicSharedMemorySize, G1_SMEM);
    cudaFuncSetAttribute(mlp2_kernel, cudaFuncAttributeMaxDynamicSharedMemorySize, M2_SMEM);

    prep_kernel<<<512, 256>>>(es, ed, emb, gcw, gcb, W1, W2, W3);
    gconv_kernel<<<B_TOTAL / GC_ROWS, 256>>>(apps);
    gemm1_kernel<<<B_TOTAL / 64, 256, G1_SMEM>>>(x, b1);
    mlp2_kernel<<<B_TOTAL / 64, 256, M2_SMEM>>>(b2, b3, b4, W4, out);
}

// round 9
// speedup vs baseline: 2.0748x; 1.1854x over previous
#include <cuda_runtime.h>
#include <cuda_fp16.h>
#include <cstdint>

#define B_TOTAL 16384
#define NNODES  200
#define NEDGES  800
#define XF      2600
#define FEATR   2800
#define FEATP   2816          // K padded to 44*64
#define NT1     (FEATP / 64)  // 44

// ---------------- device scratch ----------------
__device__ __align__(16) __half g_a1h[(size_t)B_TOTAL * 128];
__device__ float g_norm_dst[NNODES];
__device__ float g_norm_src[NNODES];
__device__ float g_ew[3];
__device__ float g_b1adj[128];
__device__ __align__(16) float g_w1gp[NNODES * 128];   // M^T @ W1g, fp32 accum
__device__ __align__(16) __half g_w1t[128 * FEATP];    // fp16, transposed [n][k]
__device__ __align__(16) __half g_w2t[128 * 128];
__device__ __align__(16) __half g_w3t[64 * 128];

// ---------------- helpers ----------------
__device__ __forceinline__ uint32_t smem_to_u32(const void* p) {
    uint32_t a;
    asm("{ .reg .u64 t; cvta.to.shared.u64 t, %1; cvt.u32.u64 %0, t; }" : "=r"(a) : "l"(p));
    return a;
}
#define SWZ(off) ((off) ^ (((off) >> 3) & 0x70))

__device__ __forceinline__ void ldsm4(uint32_t r[4], uint32_t addr) {
    asm volatile("ldmatrix.sync.aligned.m8n8.x4.shared.b16 {%0,%1,%2,%3}, [%4];"
                 : "=r"(r[0]), "=r"(r[1]), "=r"(r[2]), "=r"(r[3]) : "r"(addr));
}
__device__ __forceinline__ void mma16816h(float c[4], const uint32_t a[4],
                                          uint32_t b0, uint32_t b1) {
    asm volatile("mma.sync.aligned.m16n8k16.row.col.f32.f16.f16.f32 "
                 "{%0,%1,%2,%3}, {%4,%5,%6,%7}, {%8,%9}, {%0,%1,%2,%3};"
                 : "+f"(c[0]), "+f"(c[1]), "+f"(c[2]), "+f"(c[3])
                 : "r"(a[0]), "r"(a[1]), "r"(a[2]), "r"(a[3]), "r"(b0), "r"(b1));
}
__device__ __forceinline__ void cpa16(uint32_t dst, const void* src) {
    asm volatile("cp.async.cg.shared.global [%0], [%1], 16;" :: "r"(dst), "l"(src));
}
#define CPA_COMMIT() asm volatile("cp.async.commit_group;" ::: "memory")
#define CPA_WAIT0()  asm volatile("cp.async.wait_group 0;" ::: "memory")
#define CPA_WAIT1()  asm volatile("cp.async.wait_group 1;" ::: "memory")

__device__ __forceinline__ uint32_t packh2(float a, float b) {
    __half2 h = __floats2half2_rn(a, b);
    return *reinterpret_cast<uint32_t*>(&h);
}
__device__ __forceinline__ float softplusf(float x) {
    return fmaxf(x, 0.f) + log1pf(expf(-fabsf(x)));
}

// ---------------- MMA chunk, single-product fp16 ----------------
template<int NTILES>
__device__ __forceinline__ void mma_chunk1(float (&C)[2][NTILES][4],
                                           uint32_t a_u, uint32_t b_u,
                                           int wm_base, int wn_base, int lane) {
    const int lr = (lane & 7) + ((lane >> 3) & 1) * 8;
    const int lh = (lane >> 4) * 16;
    #pragma unroll
    for (int kk = 0; kk < 4; kk++) {
        uint32_t a[2][4];
        #pragma unroll
        for (int mt = 0; mt < 2; mt++) {
            uint32_t off = SWZ((uint32_t)((wm_base + mt * 16 + lr) * 128 + kk * 32 + lh));
            ldsm4(a[mt], a_u + off);
        }
        #pragma unroll
        for (int ng = 0; ng < NTILES / 2; ng++) {
            uint32_t off = SWZ((uint32_t)((wn_base + ng * 16 + lr) * 128 + kk * 32 + lh));
            uint32_t b[4];
            ldsm4(b, b_u + off);
            #pragma unroll
            for (int half = 0; half < 2; half++) {
                const int nt = ng * 2 + half;
                #pragma unroll
                for (int mt = 0; mt < 2; mt++)
                    mma16816h(C[mt][nt], a[mt], b[half], b[half + 2]);
            }
        }
    }
}

// ================= prep1: degrees/norms/ew/bias-fold, zero W1gp =================
__global__ void prep1_kernel(const int* __restrict__ es, const int* __restrict__ ed,
                             const float* __restrict__ emb, const float* __restrict__ gcw,
                             const float* __restrict__ gcb,
                             const float* __restrict__ W1, const float* __restrict__ b1) {
    __shared__ int cnto[NNODES], cnti[NNODES];
    const int tid = threadIdx.x;
    for (int n = tid; n < NNODES; n += 256) { cnto[n] = 0; cnti[n] = 0; }
    __syncthreads();
    for (int e = tid; e < NEDGES; e += 256) {
        atomicAdd(&cnto[es[e]], 1);
        atomicAdd(&cnti[ed[e]], 1);
    }
    __syncthreads();
    for (int n = tid; n < NNODES; n += 256) {
        g_norm_dst[n] = rsqrtf((float)max(cnti[n], 1));
        g_norm_src[n] = rsqrtf((float)max(cnto[n], 1));
    }
    if (tid < 3) {
        float s = 0.f;
        #pragma unroll
        for (int j = 0; j < 5; j++) s += emb[tid * 5 + j] * gcw[j];
        g_ew[tid] = s;
    }
    // zero W1gp
    for (int i = tid; i < NNODES * 128; i += 256) g_w1gp[i] = 0.f;
    // b1adj[n] = b1[n] + gcb * sum_d W1[(2600+d)*128 + n]
    if (tid < 128) {
        float s = 0.f;
        for (int d = 0; d < NNODES; d++) s += W1[(size_t)(XF + d) * 128 + tid];
        g_b1adj[tid] = b1[tid] + gcb[0] * s;
    }
}

// ================= prep2: weight transposes + edge atomics =================
__global__ void prep2_kernel(const int* __restrict__ es, const int* __restrict__ ed,
                             const float* __restrict__ W1, const float* __restrict__ W2,
                             const float* __restrict__ W3) {
    const int gtid = blockIdx.x * blockDim.x + threadIdx.x;
    const int gsz = gridDim.x * blockDim.x;
    // (a) edge atomics: W1gp[src][n] += c_e * W1g[dst][n]
    for (int i = gtid; i < NEDGES * 128; i += gsz) {
        const int e = i >> 7, n = i & 127;
        const int s = es[e], d = ed[e];
        const float c = g_norm_src[s] * g_norm_dst[d];
        atomicAdd(&g_w1gp[s * 128 + n], c * W1[(size_t)(XF + d) * 128 + n]);
    }
    // (b) transposes (skip W1 rows [2600,2800) — prep3 fills from W1gp)
    const int T1 = 128 * FEATP, T2 = 128 * 128, T3 = 64 * 128;
    for (int i = gtid; i < T1 + T2 + T3; i += gsz) {
        float v;
        __half* ph;
        if (i < T1) {
            int k = i % FEATP;
            int n = i / FEATP;
            if (k >= XF && k < FEATR) continue;
            v = (k < XF) ? W1[(size_t)k * 128 + n] : 0.f;
            ph = g_w1t + i;
        } else if (i < T1 + T2) {
            int j = i - T1;
            int n = j >> 7, k = j & 127;
            v = W2[k * 128 + n];
            ph = g_w2t + j;
        } else {
            int j = i - T1 - T2;
            int n = j >> 7, k = j & 127;
            v = W3[k * 64 + n];
            ph = g_w3t + j;
        }
        *ph = __float2half_rn(v);
    }
}

// ================= prep3: W1gp -> fp16 into w1t rows [2600,2800) =================
__global__ void prep3_kernel() {
    const int gtid = blockIdx.x * blockDim.x + threadIdx.x;
    if (gtid < NNODES * 128) {
        const int s = gtid >> 7, n = gtid & 127;
        g_w1t[(size_t)n * FEATP + XF + s] = __float2half_rn(g_w1gp[gtid]);
    }
}

// ================= GEMM1: a1 = softplus([x|hw] @ W1' + b1adj) -> fp16 =================
#define G1_OFF_B1 0
#define G1_OFF_A  1024                   // 2 stages x 8KB = 16KB
#define G1_OFF_BW (1024 + 16384)         // 3 stages x 16KB = 48KB
#define G1_SMEM   (1024 + 16384 + 49152)

__device__ __forceinline__ float4 app4(const int* p, float e0, float e1, float e2) {
    int4 a = *(const int4*)p;
    return make_float4(a.x == 0 ? e0 : (a.x == 1 ? e1 : e2),
                       a.y == 0 ? e0 : (a.y == 1 ? e1 : e2),
                       a.z == 0 ? e0 : (a.z == 1 ? e1 : e2),
                       a.w == 0 ? e0 : (a.w == 1 ? e1 : e2));
}

__device__ __forceinline__ void g1_lda(float4 (&pf)[4], const float* __restrict__ xr,
                                       const int* __restrict__ ar,
                                       float e0, float e1, float e2, int k0, int kq0) {
    if (k0 + 63 < XF) {
        #pragma unroll
        for (int j = 0; j < 4; j++) pf[j] = *(const float4*)(xr + k0 + kq0 + j * 4);
    } else {
        #pragma unroll
        for (int j = 0; j < 4; j++) {
            const int k = k0 + kq0 + j * 4;
            if (k + 3 < XF)       pf[j] = *(const float4*)(xr + k);
            else if (k < FEATR)   pf[j] = app4(ar + (k - XF), e0, e1, e2);
            else                  pf[j] = make_float4(0.f, 0.f, 0.f, 0.f);
        }
    }
}
__device__ __forceinline__ void g1_sta(const float4 (&pf)[4], char* Ab, int row, int kq0) {
    #pragma unroll
    for (int q = 0; q < 2; q++) {
        const float4 f0 = pf[q * 2], f1 = pf[q * 2 + 1];
        uint4 h;
        h.x = packh2(f0.x, f0.y);
        h.y = packh2(f0.z, f0.w);
        h.z = packh2(f1.x, f1.y);
        h.w = packh2(f1.z, f1.w);
        const uint32_t off = SWZ((uint32_t)(row * 128 + (kq0 + q * 8) * 2));
        *(uint4*)(Ab + off) = h;
    }
}

__global__ __launch_bounds__(256, 2)
void gemm1_kernel(const float* __restrict__ x, const int* __restrict__ apps) {
    extern __shared__ char sm[];
    const uint32_t su = smem_to_u32(sm);
    const int tid = threadIdx.x;
    const int wid = tid >> 5;
    const int lane = tid & 31;
    const int b0 = blockIdx.x * 64;

    float* sb1 = (float*)(sm + G1_OFF_B1);
    if (tid < 128) sb1[tid] = g_b1adj[tid];

    char* pA[2] = { sm + G1_OFF_A, sm + G1_OFF_A + 8192 };
    const uint32_t uA[2] = { su + G1_OFF_A, su + G1_OFF_A + 8192 };
    uint32_t uB[3];
    #pragma unroll
    for (int s = 0; s < 3; s++) uB[s] = su + G1_OFF_BW + s * 16384;

    const int arow = tid >> 2;
    const int kq0  = (tid & 3) * 16;
    const float* xr = x + (size_t)(b0 + arow) * XF;
    const int*   ar = apps + (size_t)(b0 + arow) * NNODES;
    const float e0 = g_ew[0], e1 = g_ew[1], e2 = g_ew[2];

    uint32_t bofs[4];
    const __half* gw[4];
    #pragma unroll
    for (int i = 0; i < 4; i++) {
        const int v = tid + i * 256;
        bofs[i] = SWZ((uint32_t)((v >> 3) * 128 + (v & 7) * 16));
        gw[i] = g_w1t + (size_t)(v >> 3) * FEATP + (v & 7) * 8;
    }

    const int wm = (wid >> 2) * 32;   // 2 M-groups of 32
    const int wn = (wid & 3) * 32;    // 4 N-groups of 32

    float C[2][4][4];
    #pragma unroll
    for (int i = 0; i < 2; i++)
        #pragma unroll
        for (int j = 0; j < 4; j++)
            #pragma unroll
            for (int q = 0; q < 4; q++) C[i][j][q] = 0.f;

    float4 pf[4];
    // ---- prologue ----
    #pragma unroll
    for (int i = 0; i < 4; i++) cpa16(uB[0] + bofs[i], gw[i]);
    CPA_COMMIT();
    #pragma unroll
    for (int i = 0; i < 4; i++) cpa16(uB[1] + bofs[i], gw[i] + 64);
    CPA_COMMIT();
    g1_lda(pf, xr, ar, e0, e1, e2, 0, kq0);
    g1_sta(pf, pA[0], arow, kq0);
    g1_lda(pf, xr, ar, e0, e1, e2, 64, kq0);
    CPA_WAIT1();
    __syncthreads();

    // ---- mainloop ----
    for (int t = 0; t < NT1; t++) {
        const int cur = t & 1;
        const int bs = t - (t / 3) * 3;
        const bool more2 = (t + 2 < NT1);
        if (more2) {
            const int koff = (t + 2) * 64;
            const int ns = (t + 2) - ((t + 2) / 3) * 3;
            #pragma unroll
            for (int i = 0; i < 4; i++) cpa16(uB[ns] + bofs[i], gw[i] + koff);
            CPA_COMMIT();
        }
        if (t + 1 < NT1)
            g1_sta(pf, pA[cur ^ 1], arow, kq0);
        if (more2)
            g1_lda(pf, xr, ar, e0, e1, e2, (t + 2) * 64, kq0);
        mma_chunk1<4>(C, uA[cur], uB[bs], wm, wn, lane);
        if (more2) CPA_WAIT1(); else CPA_WAIT0();
        __syncthreads();
    }

    // ---- epilogue: bias + softplus -> g_a1h (fp16) ----
    {
        const int r0 = wm + (lane >> 2);
        const int c0 = wn + (lane & 3) * 2;
        #pragma unroll
        for (int mt = 0; mt < 2; mt++) {
            #pragma unroll
            for (int nt = 0; nt < 4; nt++) {
                const int c = c0 + nt * 8;
                const float bb0 = sb1[c], bb1 = sb1[c + 1];
                uint32_t p01 = packh2(softplusf(C[mt][nt][0] + bb0),
                                      softplusf(C[mt][nt][1] + bb1));
                uint32_t p23 = packh2(softplusf(C[mt][nt][2] + bb0),
                                      softplusf(C[mt][nt][3] + bb1));
                *(uint32_t*)(g_a1h + (size_t)(b0 + r0 + mt * 16) * 128 + c) = p01;
                *(uint32_t*)(g_a1h + (size_t)(b0 + r0 + mt * 16 + 8) * 128 + c) = p23;
            }
        }
    }
}

// ================= kernel 2: layers 2-4 (unchanged from R8) =================
#define M2_OFF_B2 0
#define M2_OFF_B3 512
#define M2_OFF_B4 768
#define M2_OFF_W4 1024
#define M2_OFF_A  2048
#define M2_OFF_BW (2048 + 16384)
#define M2_SMEM   (2048 + 16384 + 32768)

__device__ __forceinline__ void m2_cpa_W(const __half* __restrict__ W, int ldk,
                                         int k0, uint32_t dst, int nrows, int tid) {
    const int nv = nrows * 8;
    for (int v = tid; v < nv; v += 256) {
        const int n = v >> 3, kq = (v & 7) * 8;
        cpa16(dst + SWZ((uint32_t)(n * 128 + kq * 2)), W + (size_t)n * ldk + k0 + kq);
    }
}

__device__ __forceinline__ void m2_epi(float (&C)[2][4][4], const float* bias,
                                       char* dst, int wm_base, int wn_base, int lane) {
    const int r0 = wm_base + (lane >> 2);
    const int c0 = wn_base + (lane & 3) * 2;
    #pragma unroll
    for (int mt = 0; mt < 2; mt++) {
        #pragma unroll
        for (int nt = 0; nt < 4; nt++) {
            const int n = c0 + nt * 8;
            const int chunk = n >> 6, col = n & 63;
            const float b0 = bias[n], b1 = bias[n + 1];
            char* td = dst + chunk * 8192;
            uint32_t p01 = packh2(softplusf(C[mt][nt][0] + b0),
                                  softplusf(C[mt][nt][1] + b1));
            uint32_t p23 = packh2(softplusf(C[mt][nt][2] + b0),
                                  softplusf(C[mt][nt][3] + b1));
            *(uint32_t*)(td + SWZ((uint32_t)((r0 + mt * 16) * 128 + col * 2))) = p01;
            *(uint32_t*)(td + SWZ((uint32_t)((r0 + mt * 16 + 8) * 128 + col * 2))) = p23;
        }
    }
}

__global__ __launch_bounds__(256, 2)
void mlp2_kernel(const float* __restrict__ b2g, const float* __restrict__ b3g,
                 const float* __restrict__ b4g, const float* __restrict__ W4g,
                 float* __restrict__ out) {
    extern __shared__ char sm[];
    const uint32_t su = smem_to_u32(sm);
    const int tid = threadIdx.x;
    const int wid = tid >> 5;
    const int lane = tid & 31;
    const int b0 = blockIdx.x * 64;

    float* sb2 = (float*)(sm + M2_OFF_B2);
    float* sb3 = (float*)(sm + M2_OFF_B3);
    float* sb4 = (float*)(sm + M2_OFF_B4);
    float* sW4 = (float*)(sm + M2_OFF_W4);
    if (tid < 128) { sb2[tid] = b2g[tid]; sW4[tid] = W4g[tid]; }
    if (tid < 64) sb3[tid] = b3g[tid];
    if (tid < 2) sb4[tid] = b4g[tid];

    const uint32_t uA[2] = { su + M2_OFF_A, su + M2_OFF_A + 8192 };
    const uint32_t uB[2] = { su + M2_OFF_BW, su + M2_OFF_BW + 16384 };

    m2_cpa_W(g_a1h + (size_t)b0 * 128, 128, 0,  uA[0], 64, tid);
    m2_cpa_W(g_a1h + (size_t)b0 * 128, 128, 64, uA[1], 64, tid);
    m2_cpa_W(g_w2t, 128, 0,  uB[0], 128, tid);
    m2_cpa_W(g_w2t, 128, 64, uB[1], 128, tid);
    CPA_COMMIT();
    CPA_WAIT0();
    __syncthreads();

    const int wm = (wid >> 2) * 32;
    const int wn = (wid & 3) * 32;

    float C[2][4][4];
    #pragma unroll
    for (int i = 0; i < 2; i++)
        #pragma unroll
        for (int j = 0; j < 4; j++)
            #pragma unroll
            for (int q = 0; q < 4; q++) C[i][j][q] = 0.f;
    #pragma unroll
    for (int c = 0; c < 2; c++)
        mma_chunk1<4>(C, uA[c], uB[c], wm, wn, lane);
    __syncthreads();

    m2_epi(C, sb2, sm + M2_OFF_A, wm, wn, lane);
    m2_cpa_W(g_w3t, 128, 0,  su + M2_OFF_BW,        64, tid);
    m2_cpa_W(g_w3t, 128, 64, su + M2_OFF_BW + 8192, 64, tid);
    CPA_COMMIT();
    CPA_WAIT0();
    __syncthreads();

    const int wn3 = (wid & 3) * 16;
    float C3[2][2][4];
    #pragma unroll
    for (int i = 0; i < 2; i++)
        #pragma unroll
        for (int j = 0; j < 2; j++)
            #pragma unroll
            for (int q = 0; q < 4; q++) C3[i][j][q] = 0.f;
    #pragma unroll
    for (int c = 0; c < 2; c++)
        mma_chunk1<2>(C3, uA[c], su + M2_OFF_BW + c * 8192, wm, wn3, lane);
    __syncthreads();

    {
        float* a3 = (float*)(sm + M2_OFF_A);
        const int r0 = wm + (lane >> 2);
        const int c0 = wn3 + (lane & 3) * 2;
        #pragma unroll
        for (int mt = 0; mt < 2; mt++) {
            #pragma unroll
            for (int nt = 0; nt < 2; nt++) {
                const int n = c0 + nt * 8;
                const float b0v = sb3[n], b1v = sb3[n + 1];
                float v;
                v = C3[mt][nt][0] + b0v; a3[(r0 + mt * 16) * 68 + n]     = v - tanhf(v);
                v = C3[mt][nt][1] + b1v; a3[(r0 + mt * 16) * 68 + n + 1] = v - tanhf(v);
                v = C3[mt][nt][2] + b0v; a3[(r0 + mt * 16 + 8) * 68 + n]     = v - tanhf(v);
                v = C3[mt][nt][3] + b1v; a3[(r0 + mt * 16 + 8) * 68 + n + 1] = v - tanhf(v);
            }
        }
    }
    __syncthreads();

    if (tid < 128) {
        const float* a3 = (const float*)(sm + M2_OFF_A);
        const int row = tid >> 1;
        const int c = tid & 1;
        float s = sb4[c];
        #pragma unroll
        for (int k = 0; k < 64; k++) s += a3[row * 68 + k] * sW4[k * 2 + c];
        out[(size_t)(b0 + row) * 2 + c] = 1.f / (1.f + expf(-s));
    }
}

// ---------------- launch ----------------
extern "C" void kernel_launch(void* const* d_in, const int* in_sizes, int n_in,
                              void* d_out, int out_size) {
    const float* x    = (const float*)d_in[0];
    const int*   apps = (const int*)d_in[1];
    const int*   es   = (const int*)d_in[2];
    const int*   ed   = (const int*)d_in[3];
    const float* emb  = (const float*)d_in[4];
    const float* gcw  = (const float*)d_in[5];
    const float* gcb  = (const float*)d_in[6];
    const float* W1   = (const float*)d_in[7];
    const float* b1   = (const float*)d_in[8];
    const float* W2   = (const float*)d_in[9];
    const float* b2   = (const float*)d_in[10];
    const float* W3   = (const float*)d_in[11];
    const float* b3   = (const float*)d_in[12];
    const float* W4   = (const float*)d_in[13];
    const float* b4   = (const float*)d_in[14];
    float* out = (float*)d_out;

    cudaFuncSetAttribute(gemm1_kernel, cudaFuncAttributeMaxDynamicSharedMemorySize, G1_SMEM);
    cudaFuncSetAttribute(mlp2_kernel, cudaFuncAttributeMaxDynamicSharedMemorySize, M2_SMEM);

    prep1_kernel<<<1, 256>>>(es, ed, emb, gcw, gcb, W1, b1);
    prep2_kernel<<<512, 256>>>(es, ed, W1, W2, W3);
    prep3_kernel<<<100, 256>>>();
    gemm1_kernel<<<B_TOTAL / 64, 256, G1_SMEM>>>(x, apps);
    mlp2_kernel<<<B_TOTAL / 64, 256, M2_SMEM>>>(b2, b3, b4, W4, out);
}